// round 4
// baseline (speedup 1.0000x reference)
#include <cuda_runtime.h>
#include <cstdint>

// Problem constants
#define BATCH 32
#define NNODE 4096
#define INDIM 64
#define HDIM  128

// GEMM tile config
#define BM 128
#define BN 128
#define BK 16
#define SA_STRIDE 20    // 16 + 4 pad -> conflict-free for A-frag quad pattern
#define SB_STRIDE 136   // 128 + 8 pad -> conflict-free for B-frag quad pattern

// Scratch: t (post-gcn1) and agg. h lives in d_out (in-place Euler update is
// element-wise safe). 64 MB each.
__device__ __align__(256) float g_t[(size_t)BATCH * NNODE * HDIM];
__device__ __align__(256) float g_agg[(size_t)BATCH * NNODE * HDIM];

__device__ __forceinline__ uint32_t cvt_tf32(float x) {
    uint32_t r;
    asm("cvt.rna.tf32.f32 %0, %1;" : "=r"(r) : "f"(x));
    return r;
}

__device__ __forceinline__ void mma_tf32(float c[4],
                                         uint32_t a0, uint32_t a1, uint32_t a2, uint32_t a3,
                                         uint32_t b0, uint32_t b1) {
    asm volatile(
        "mma.sync.aligned.m16n8k8.row.col.f32.tf32.tf32.f32 "
        "{%0,%1,%2,%3}, {%4,%5,%6,%7}, {%8,%9}, {%0,%1,%2,%3};\n"
        : "+f"(c[0]), "+f"(c[1]), "+f"(c[2]), "+f"(c[3])
        : "r"(a0), "r"(a1), "r"(a2), "r"(a3), "r"(b0), "r"(b1));
}

__device__ __forceinline__ void cp_async16(void* smem, const void* gmem) {
    uint32_t s = (uint32_t)__cvta_generic_to_shared(smem);
    asm volatile("cp.async.cg.shared.global [%0], [%1], 16;\n" :: "r"(s), "l"(gmem));
}
#define CP_COMMIT() asm volatile("cp.async.commit_group;\n" ::: "memory")
#define CP_WAIT0()  asm volatile("cp.async.wait_group 0;\n" ::: "memory")

// Generic TF32 GEMM: C[M,N] = A[M,K] @ B[K,N] (all row-major), batched over z.
// mode 0: C = acc                        (aggregation, no bias)
// mode 1: C = relu(acc + bias)          (gcn1 projection)
// mode 2: C = Cin + 0.25*relu(acc+bias) (gcn2 projection + Euler step)
// mode 3: C = acc + bias                (fc)
__global__ __launch_bounds__(256, 2)
void gemm_tf32_kernel(const float* __restrict__ A, const float* __restrict__ Bm,
                      const float* __restrict__ Cin, float* __restrict__ C,
                      const float* __restrict__ bias,
                      int M, int N, int K,
                      long long sA, long long sB, long long sC, long long sCin,
                      int mode)
{
    // 16-byte alignment is REQUIRED for cp.async.cg ... 16 destinations.
    __shared__ __align__(16) float As[2][BM * SA_STRIDE];
    __shared__ __align__(16) float Bs[2][BK * SB_STRIDE];

    const int bz = blockIdx.z;
    A  += (long long)bz * sA;
    Bm += (long long)bz * sB;
    C  += (long long)bz * sC;
    const float* Cin_b = Cin ? (Cin + (long long)bz * sCin) : nullptr;

    const int bm = blockIdx.y * BM;
    const int bn = blockIdx.x * BN;

    const int tid  = threadIdx.x;
    const int lane = tid & 31;
    const int warp = tid >> 5;
    const int wm = (warp & 3) * 32;   // 4 warps along M (4*32 = 128)
    const int wn = (warp >> 2) * 64;  // 2 warps along N (2*64 = 128)
    const int g = lane >> 2;          // group id 0..7
    const int t = lane & 3;           // thread-in-group 0..3

    float acc[2][8][4];
    #pragma unroll
    for (int mt = 0; mt < 2; mt++)
        #pragma unroll
        for (int nt = 0; nt < 8; nt++)
            #pragma unroll
            for (int i = 0; i < 4; i++)
                acc[mt][nt][i] = 0.0f;

    auto load_stage = [&](int stage, int kt) {
        const float* Ag = A + (long long)bm * K + (long long)kt * BK;
        #pragma unroll
        for (int i = 0; i < 2; i++) {
            int idx = tid + i * 256;
            int r = idx >> 2;
            int c = (idx & 3) << 2;
            cp_async16(&As[stage][r * SA_STRIDE + c], Ag + (long long)r * K + c);
        }
        const float* Bg = Bm + (long long)(kt * BK) * N + bn;
        #pragma unroll
        for (int i = 0; i < 2; i++) {
            int idx = tid + i * 256;
            int r = idx >> 5;
            int c = (idx & 31) << 2;
            cp_async16(&Bs[stage][r * SB_STRIDE + c], Bg + (long long)r * N + c);
        }
    };

    auto compute_stage = [&](int stage) {
        #pragma unroll
        for (int ks = 0; ks < BK; ks += 8) {
            uint32_t af[2][4];
            #pragma unroll
            for (int mt = 0; mt < 2; mt++) {
                const int rb = wm + mt * 16;
                const float* as = &As[stage][0];
                af[mt][0] = cvt_tf32(as[(rb + g)     * SA_STRIDE + ks + t]);
                af[mt][1] = cvt_tf32(as[(rb + g + 8) * SA_STRIDE + ks + t]);
                af[mt][2] = cvt_tf32(as[(rb + g)     * SA_STRIDE + ks + t + 4]);
                af[mt][3] = cvt_tf32(as[(rb + g + 8) * SA_STRIDE + ks + t + 4]);
            }
            uint32_t bf[8][2];
            #pragma unroll
            for (int nt = 0; nt < 8; nt++) {
                const int nb = wn + nt * 8 + g;
                const float* bs = &Bs[stage][0];
                bf[nt][0] = cvt_tf32(bs[(ks + t)     * SB_STRIDE + nb]);
                bf[nt][1] = cvt_tf32(bs[(ks + t + 4) * SB_STRIDE + nb]);
            }
            #pragma unroll
            for (int mt = 0; mt < 2; mt++)
                #pragma unroll
                for (int nt = 0; nt < 8; nt++)
                    mma_tf32(acc[mt][nt], af[mt][0], af[mt][1], af[mt][2], af[mt][3],
                             bf[nt][0], bf[nt][1]);
        }
    };

    const int nk = K / BK;
    load_stage(0, 0);
    CP_COMMIT();
    CP_WAIT0();
    __syncthreads();

    for (int kt = 0; kt < nk; kt++) {
        const int s = kt & 1;
        if (kt + 1 < nk) {
            load_stage(s ^ 1, kt + 1);
            CP_COMMIT();
        }
        compute_stage(s);
        if (kt + 1 < nk) {
            CP_WAIT0();
            __syncthreads();
        }
    }

    // Epilogue
    #pragma unroll
    for (int mt = 0; mt < 2; mt++) {
        #pragma unroll
        for (int nt = 0; nt < 8; nt++) {
            #pragma unroll
            for (int half = 0; half < 2; half++) {
                const int row = bm + wm + mt * 16 + g + half * 8;
                const int col = bn + wn + nt * 8 + t * 2;
                float v0 = acc[mt][nt][half * 2 + 0];
                float v1 = acc[mt][nt][half * 2 + 1];
                const long long off = (long long)row * N + col;
                float2 out;
                if (mode == 0) {
                    out.x = v0; out.y = v1;
                } else {
                    v0 += bias[col];
                    v1 += bias[col + 1];
                    if (mode == 1) {
                        out.x = fmaxf(v0, 0.0f);
                        out.y = fmaxf(v1, 0.0f);
                    } else if (mode == 2) {
                        out.x = Cin_b[off]     + 0.25f * fmaxf(v0, 0.0f);
                        out.y = Cin_b[off + 1] + 0.25f * fmaxf(v1, 0.0f);
                    } else { // mode 3
                        out.x = v0; out.y = v1;
                    }
                }
                *reinterpret_cast<float2*>(&C[off]) = out;
            }
        }
    }
}

extern "C" void kernel_launch(void* const* d_in, const int* in_sizes, int n_in,
                              void* d_out, int out_size)
{
    const float* x    = (const float*)d_in[0];
    const float* adj  = (const float*)d_in[1];
    const float* W_fc = (const float*)d_in[2];
    const float* b_fc = (const float*)d_in[3];
    const float* W1   = (const float*)d_in[4];
    const float* b1   = (const float*)d_in[5];
    const float* W2   = (const float*)d_in[6];
    const float* b2   = (const float*)d_in[7];
    float* out = (float*)d_out;

    // h lives in d_out; t/agg in device globals.
    float *t, *agg;
    cudaGetSymbolAddress((void**)&t,   g_t);
    cudaGetSymbolAddress((void**)&agg, g_agg);
    float* h = out;

    const long long sNH = (long long)NNODE * HDIM;  // per-batch stride
    dim3 blk(256);

    // h = x @ W_fc + b_fc   : M = B*N, K = 64, N = 128
    gemm_tf32_kernel<<<dim3(1, (BATCH * NNODE) / BM, 1), blk>>>(
        x, W_fc, nullptr, h, b_fc,
        BATCH * NNODE, HDIM, INDIM, 0, 0, 0, 0, 3);

    for (int step = 0; step < 4; step++) {
        // agg = adj @ h  (batched over z)
        gemm_tf32_kernel<<<dim3(1, NNODE / BM, BATCH), blk>>>(
            adj, h, nullptr, agg, nullptr,
            NNODE, HDIM, NNODE, 0, sNH, sNH, 0, 0);
        // t = relu(agg @ W1 + b1)
        gemm_tf32_kernel<<<dim3(1, (BATCH * NNODE) / BM, 1), blk>>>(
            agg, W1, nullptr, t, b1,
            BATCH * NNODE, HDIM, HDIM, 0, 0, 0, 0, 1);
        // agg = adj @ t  (batched over z)
        gemm_tf32_kernel<<<dim3(1, NNODE / BM, BATCH), blk>>>(
            adj, t, nullptr, agg, nullptr,
            NNODE, HDIM, NNODE, 0, sNH, sNH, 0, 0);
        // h = h + 0.25 * relu(agg @ W2 + b2)   (in-place, element-wise safe)
        gemm_tf32_kernel<<<dim3(1, (BATCH * NNODE) / BM, 1), blk>>>(
            agg, W2, h, h, b2,
            BATCH * NNODE, HDIM, HDIM, 0, 0, 0, 0, 2);
    }
}

// round 7
// speedup vs baseline: 1.1468x; 1.1468x over previous
#include <cuda_runtime.h>
#include <cstdint>

// Problem constants
#define BATCH 32
#define NNODE 4096
#define INDIM 64
#define HDIM  128

// GEMM tile config (static smem, proven in R4)
#define BM 128
#define BN 128
#define BK 16
#define SA_STRIDE 20    // 16 + 4 pad -> conflict-free frag LDS
#define SB_STRIDE 136   // 128 + 8 pad -> conflict-free frag LDS

// ---------------------------------------------------------------------------
// SINGLE device global, 128 MB + 160 KB (R4's proven footprint was 128 MB;
// >128 MB of globals correlates 4/4 with container kills). Carved into:
//   [0,               BNH)   : agg   (tf32-rounded aggregation output)
//   [BNH,           2*BNH)   : t/hr  (dual-purpose: rounded gcn1 output OR
//                                     rounded shadow of h; liveness disjoint)
//   [2*BNH, 2*BNH+40960)     : rounded W_fc (8192) | W1 (16384) | W2 (16384)
// h itself (fp32, Euler state) lives in d_out.
// ---------------------------------------------------------------------------
#define BNH ((size_t)BATCH * NNODE * HDIM)
#define W_OFF (2 * BNH)
__device__ __align__(256) float g_scratch[2 * BNH + 40960];

__device__ __forceinline__ uint32_t cvt_tf32(float x) {
    uint32_t r;
    asm("cvt.rna.tf32.f32 %0, %1;" : "=r"(r) : "f"(x));
    return r;
}
__device__ __forceinline__ float round_tf32(float x) {
    return __uint_as_float(cvt_tf32(x));
}

__device__ __forceinline__ void mma_tf32(float c[4],
                                         uint32_t a0, uint32_t a1, uint32_t a2, uint32_t a3,
                                         uint32_t b0, uint32_t b1) {
    asm volatile(
        "mma.sync.aligned.m16n8k8.row.col.f32.tf32.tf32.f32 "
        "{%0,%1,%2,%3}, {%4,%5,%6,%7}, {%8,%9}, {%0,%1,%2,%3};\n"
        : "+f"(c[0]), "+f"(c[1]), "+f"(c[2]), "+f"(c[3])
        : "r"(a0), "r"(a1), "r"(a2), "r"(a3), "r"(b0), "r"(b1));
}

__device__ __forceinline__ void cp_async16(void* smem, const void* gmem) {
    uint32_t s = (uint32_t)__cvta_generic_to_shared(smem);
    asm volatile("cp.async.cg.shared.global [%0], [%1], 16;\n" :: "r"(s), "l"(gmem));
}
#define CP_COMMIT() asm volatile("cp.async.commit_group;\n" ::: "memory")
#define CP_WAIT0()  asm volatile("cp.async.wait_group 0;\n" ::: "memory")

// Element-wise tf32 rounding pre-pass for the small weight matrices.
__global__ void round_copy_kernel(const float* __restrict__ in, float* __restrict__ out, int n4) {
    int i = blockIdx.x * blockDim.x + threadIdx.x;
    if (i < n4) {
        float4 v = reinterpret_cast<const float4*>(in)[i];
        v.x = round_tf32(v.x); v.y = round_tf32(v.y);
        v.z = round_tf32(v.z); v.w = round_tf32(v.w);
        reinterpret_cast<float4*>(out)[i] = v;
    }
}

// Generic TF32 GEMM: C[M,N] = A[M,K] @ B[K,N] (row-major), batched over z.
// B must be pre-rounded to tf32. A is pre-rounded iff CVT_A == 0; otherwise
// A-fragments are rounded (rna) in the mainloop.
// mode 0: C = round(acc)                                  (aggregation)
// mode 1: C = round(relu(acc + bias))                     (gcn1 projection -> t)
// mode 2: C = Cin + 0.25*relu(acc+bias); Cr = round(C)    (gcn2 + Euler, dual write)
// mode 3: C = acc + bias;                Cr = round(C)    (fc, dual write)
template <int CVT_A>
__global__ __launch_bounds__(256, 2)
void gemm_tf32_kernel(const float* __restrict__ A, const float* __restrict__ Bm,
                      const float* __restrict__ Cin, float* __restrict__ C,
                      float* __restrict__ Cr,
                      const float* __restrict__ bias,
                      int M, int N, int K,
                      long long sA, long long sB, long long sC, long long sCin,
                      int mode)
{
    __shared__ __align__(16) float As[2][BM * SA_STRIDE];
    __shared__ __align__(16) float Bs[2][BK * SB_STRIDE];

    const int bz = blockIdx.z;
    A  += (long long)bz * sA;
    Bm += (long long)bz * sB;
    C  += (long long)bz * sC;
    float* Cr_b = Cr ? (Cr + (long long)bz * sC) : nullptr;
    const float* Cin_b = Cin ? (Cin + (long long)bz * sCin) : nullptr;

    const int bm = blockIdx.y * BM;
    const int bn = blockIdx.x * BN;

    const int tid  = threadIdx.x;
    const int lane = tid & 31;
    const int warp = tid >> 5;
    const int wm = (warp & 3) * 32;   // 4 warps along M
    const int wn = (warp >> 2) * 64;  // 2 warps along N
    const int g = lane >> 2;
    const int t = lane & 3;

    float acc[2][8][4];
    #pragma unroll
    for (int mt = 0; mt < 2; mt++)
        #pragma unroll
        for (int nt = 0; nt < 8; nt++)
            #pragma unroll
            for (int i = 0; i < 4; i++)
                acc[mt][nt][i] = 0.0f;

    auto load_stage = [&](int stage, int kt) {
        const float* Ag = A + (long long)bm * K + (long long)kt * BK;
        #pragma unroll
        for (int i = 0; i < 2; i++) {
            int idx = tid + i * 256;
            int r = idx >> 2;
            int c = (idx & 3) << 2;
            cp_async16(&As[stage][r * SA_STRIDE + c], Ag + (long long)r * K + c);
        }
        const float* Bg = Bm + (long long)(kt * BK) * N + bn;
        #pragma unroll
        for (int i = 0; i < 2; i++) {
            int idx = tid + i * 256;
            int r = idx >> 5;
            int c = (idx & 31) << 2;
            cp_async16(&Bs[stage][r * SB_STRIDE + c], Bg + (long long)r * N + c);
        }
    };

    auto rd_a = [&](const float* p) -> uint32_t {
        return CVT_A ? cvt_tf32(*p) : __float_as_uint(*p);
    };

    auto compute_stage = [&](int stage) {
        #pragma unroll
        for (int ks = 0; ks < BK; ks += 8) {
            uint32_t af[2][4];
            #pragma unroll
            for (int mt = 0; mt < 2; mt++) {
                const int rb = wm + mt * 16;
                const float* as = &As[stage][0];
                af[mt][0] = rd_a(&as[(rb + g)     * SA_STRIDE + ks + t]);
                af[mt][1] = rd_a(&as[(rb + g + 8) * SA_STRIDE + ks + t]);
                af[mt][2] = rd_a(&as[(rb + g)     * SA_STRIDE + ks + t + 4]);
                af[mt][3] = rd_a(&as[(rb + g + 8) * SA_STRIDE + ks + t + 4]);
            }
            uint32_t bf[8][2];
            #pragma unroll
            for (int nt = 0; nt < 8; nt++) {
                const int nb = wn + nt * 8 + g;
                const float* bs = &Bs[stage][0];
                bf[nt][0] = __float_as_uint(bs[(ks + t)     * SB_STRIDE + nb]);
                bf[nt][1] = __float_as_uint(bs[(ks + t + 4) * SB_STRIDE + nb]);
            }
            #pragma unroll
            for (int mt = 0; mt < 2; mt++)
                #pragma unroll
                for (int nt = 0; nt < 8; nt++)
                    mma_tf32(acc[mt][nt], af[mt][0], af[mt][1], af[mt][2], af[mt][3],
                             bf[nt][0], bf[nt][1]);
        }
    };

    const int nk = K / BK;
    load_stage(0, 0);
    CP_COMMIT();
    CP_WAIT0();
    __syncthreads();

    for (int kt = 0; kt < nk; kt++) {
        const int s = kt & 1;
        if (kt + 1 < nk) {
            load_stage(s ^ 1, kt + 1);
            CP_COMMIT();
        }
        compute_stage(s);
        if (kt + 1 < nk) {
            CP_WAIT0();
            __syncthreads();
        }
    }

    // Epilogue
    #pragma unroll
    for (int mt = 0; mt < 2; mt++) {
        #pragma unroll
        for (int nt = 0; nt < 8; nt++) {
            #pragma unroll
            for (int half = 0; half < 2; half++) {
                const int row = bm + wm + mt * 16 + g + half * 8;
                const int col = bn + wn + nt * 8 + t * 2;
                float v0 = acc[mt][nt][half * 2 + 0];
                float v1 = acc[mt][nt][half * 2 + 1];
                const long long off = (long long)row * N + col;
                float2 out;
                if (mode == 0) {
                    out.x = round_tf32(v0);
                    out.y = round_tf32(v1);
                } else if (mode == 1) {
                    out.x = round_tf32(fmaxf(v0 + bias[col],     0.0f));
                    out.y = round_tf32(fmaxf(v1 + bias[col + 1], 0.0f));
                } else if (mode == 2) {
                    float2 hin = *reinterpret_cast<const float2*>(&Cin_b[off]);
                    out.x = hin.x + 0.25f * fmaxf(v0 + bias[col],     0.0f);
                    out.y = hin.y + 0.25f * fmaxf(v1 + bias[col + 1], 0.0f);
                    float2 r2 = { round_tf32(out.x), round_tf32(out.y) };
                    *reinterpret_cast<float2*>(&Cr_b[off]) = r2;
                } else { // mode 3
                    out.x = v0 + bias[col];
                    out.y = v1 + bias[col + 1];
                    float2 r2 = { round_tf32(out.x), round_tf32(out.y) };
                    *reinterpret_cast<float2*>(&Cr_b[off]) = r2;
                }
                *reinterpret_cast<float2*>(&C[off]) = out;
            }
        }
    }
}

extern "C" void kernel_launch(void* const* d_in, const int* in_sizes, int n_in,
                              void* d_out, int out_size)
{
    const float* x    = (const float*)d_in[0];
    const float* adj  = (const float*)d_in[1];
    const float* W_fc = (const float*)d_in[2];
    const float* b_fc = (const float*)d_in[3];
    const float* W1   = (const float*)d_in[4];
    const float* b1   = (const float*)d_in[5];
    const float* W2   = (const float*)d_in[6];
    const float* b2   = (const float*)d_in[7];
    float* out = (float*)d_out;

    float* base;
    cudaGetSymbolAddress((void**)&base, g_scratch);
    float* agg   = base;                     // rounded aggregation output
    float* t_hr  = base + BNH;               // rounded t / rounded h shadow
    float* wfc_r = base + W_OFF;             // rounded W_fc (64*128)
    float* w1_r  = wfc_r + INDIM * HDIM;     // rounded W1   (128*128)
    float* w2_r  = w1_r  + HDIM * HDIM;      // rounded W2   (128*128)
    float* h = out;  // fp32 Euler state lives in d_out

    // Pre-round the small weight matrices (B operands must be pre-rounded).
    {
        const int thr = 256;
        int n4 = (INDIM * HDIM) / 4;
        round_copy_kernel<<<(n4 + thr - 1) / thr, thr>>>(W_fc, wfc_r, n4);
        n4 = (HDIM * HDIM) / 4;
        round_copy_kernel<<<(n4 + thr - 1) / thr, thr>>>(W1, w1_r, n4);
        round_copy_kernel<<<(n4 + thr - 1) / thr, thr>>>(W2, w2_r, n4);
    }

    const long long sNH = (long long)NNODE * HDIM;  // per-batch stride
    dim3 blk(256);

    // h = x @ W_fc + b_fc  (A = x unrounded -> CVT_A=1; writes fp32 h + rounded hr)
    gemm_tf32_kernel<1><<<dim3(1, (BATCH * NNODE) / BM, 1), blk>>>(
        x, wfc_r, nullptr, h, t_hr, b_fc,
        BATCH * NNODE, HDIM, INDIM, 0, 0, 0, 0, 3);

    for (int step = 0; step < 4; step++) {
        // agg = round(adj @ hr)   (A = adj unrounded -> CVT_A=1; B = hr rounded)
        gemm_tf32_kernel<1><<<dim3(1, NNODE / BM, BATCH), blk>>>(
            adj, t_hr, nullptr, agg, nullptr, nullptr,
            NNODE, HDIM, NNODE, 0, sNH, sNH, 0, 0);
        // t = round(relu(agg @ W1 + b1))   (both operands rounded -> CVT_A=0)
        gemm_tf32_kernel<0><<<dim3(1, (BATCH * NNODE) / BM, 1), blk>>>(
            agg, w1_r, nullptr, t_hr, nullptr, b1,
            BATCH * NNODE, HDIM, HDIM, 0, 0, 0, 0, 1);
        // agg = round(adj @ t)
        gemm_tf32_kernel<1><<<dim3(1, NNODE / BM, BATCH), blk>>>(
            adj, t_hr, nullptr, agg, nullptr, nullptr,
            NNODE, HDIM, NNODE, 0, sNH, sNH, 0, 0);
        // h = h + 0.25*relu(agg @ W2 + b2) (in-place fp32) + rounded shadow hr
        gemm_tf32_kernel<0><<<dim3(1, (BATCH * NNODE) / BM, 1), blk>>>(
            agg, w2_r, h, h, t_hr, b2,
            BATCH * NNODE, HDIM, HDIM, 0, 0, 0, 0, 2);
    }
}